// round 11
// baseline (speedup 1.0000x reference)
#include <cuda_runtime.h>

// StDevLoss: 7x7 clamped-window 3D-point-distance std, summed, x100.
// depthin (1,1,480,640) fp32 -> scalar fp32. Single fused kernel.
// Round 11: fully packed f32x2 inner loop (FFMA2 quadratic eval, packed
// s2 accumulators), (z,z^2) float2 smem, 2 px/thread, 1200 blocks.

#define ROWS 480
#define COLS 640

#define BX 32
#define BY 4
#define NT (BX * BY)          // 128 threads
#define PIX_Y 8               // 2 pixels per thread
#define TW (BX + 6)           // 38
#define TH (PIX_Y + 6)        // 14
#define TP 40                 // shared row stride (float2 units)

#define GRIDX (COLS / BX)     // 20
#define GRIDY (ROWS / PIX_Y)  // 60
#define NPART (GRIDX * GRIDY) // 1200

__device__ float g_partials[NPART];
__device__ unsigned int g_count = 0;

typedef unsigned long long u64;

// sqrt(|x|): abs folds into the MUFU operand modifier; sqrt.approx(0)==0.
__device__ __forceinline__ float sqrt_abs(float x) {
    float r;
    asm("{\n\t.reg .f32 t;\n\tabs.f32 t, %1;\n\tsqrt.approx.f32 %0, t;\n\t}"
        : "=f"(r) : "f"(x));
    return r;
}
__device__ __forceinline__ u64 pack2(float lo, float hi) {
    u64 r;
    asm("mov.b64 %0, {%1, %2};" : "=l"(r) : "f"(lo), "f"(hi));
    return r;
}
__device__ __forceinline__ void unpack2(u64 v, float& lo, float& hi) {
    asm("mov.b64 {%0, %1}, %2;" : "=f"(lo), "=f"(hi) : "l"(v));
}
__device__ __forceinline__ u64 add2(u64 a, u64 b) {
    u64 r;
    asm("add.rn.f32x2 %0, %1, %2;" : "=l"(r) : "l"(a), "l"(b));
    return r;
}
__device__ __forceinline__ u64 fma2(u64 a, u64 b, u64 c) {
    u64 r;
    asm("fma.rn.f32x2 %0, %1, %2, %3;" : "=l"(r) : "l"(a), "l"(b), "l"(c));
    return r;
}

__global__ __launch_bounds__(NT, 8)
void stdev_kernel(const float* __restrict__ depth, float* __restrict__ out) {
    const float CXc   = 313.0447587080473f;
    const float CYc   = 238.44389626620386f;
    const float invFX = 1.0f / 582.6244816773795f;
    const float invFY = 1.0f / 582.6910327098864f;

    __shared__ float2 shz[TH * TP];      // (z, z^2)
    __shared__ float red[NT / 32];
    __shared__ unsigned int s_last;

    const int tx  = threadIdx.x;
    const int ty  = threadIdx.y;
    const int tid = ty * BX + tx;
    const int c0  = blockIdx.x * BX;
    const int r0  = blockIdx.y * PIX_Y;

    // Cooperative haloed (z, z^2) tile load. Clamped halo cells are never
    // read by the clamped-window indexing but must hold finite values.
    for (int i = tid; i < TH * TW; i += NT) {
        const int sr = i / TW;
        const int sc = i - sr * TW;
        const int gr = min(max(r0 - 3 + sr, 0), ROWS - 1);
        const int gc = min(max(c0 - 3 + sc, 0), COLS - 1);
        const float d = depth[gr * COLS + gc];
        const float z = (d > 0.0f && d < 1.01f) ? d * 1e-3f : 0.0f;
        shz[sr * TP + sc] = make_float2(z, z * z);
    }
    __syncthreads();

    const int c    = c0 + tx;
    const int jb   = min(max(c - 3, 0), COLS - 7);
    const int jb_s = jb - c0 + 3;
    const float cfc = ((float)c - CXc) * invFX;     // center column factor
    const float cf0 = ((float)jb - CXc) * invFX;    // window column base

    float total = 0.0f;

    #pragma unroll
    for (int p = 0; p < 2; p++) {
        const int r    = r0 + ty + p * BY;
        const int ib   = min(max(r - 3, 0), ROWS - 7);
        const int ib_s = ib - r0 + 3;

        const float zc = shz[(ty + p * BY + 3) * TP + (tx + 3)].x;
        const float xc = zc * cfc;
        const float yc = zc * (((float)r - CYc) * invFY);
        float pc2 = xc * xc;
        pc2 = fmaf(yc, yc, pc2);
        pc2 = fmaf(zc, zc, pc2);
        const u64 pc2p = pack2(pc2, 0.0f);
        const float m2xc = -2.0f * xc;
        const float m2yc = -2.0f * yc;
        const float m2zc = -2.0f * zc;

        // Per-column packed (b_j, g_j): b = -2*xc*cf, g = cf^2 + 1.
        u64 bg[7];
        {
            float cf = cf0;
            #pragma unroll
            for (int j = 0; j < 7; j++) {
                bg[j] = pack2(m2xc * cf, fmaf(cf, cf, 1.0f));
                cf += invFX;
            }
        }

        float s1a = 0.0f, s1b = 0.0f;          // sum d (dual chains)
        u64 s2pa = pack2(0.0f, 0.0f);          // packed sum of (lo, hi) parts
        u64 s2pb = pack2(0.0f, 0.0f);

        float rf = ((float)ib - CYc) * invFY;
        #pragma unroll
        for (int i = 0; i < 7; i++) {
            // Per-row packed (a_i, rf^2): a = -2*(yc*rf + zc).
            const u64 ar = pack2(fmaf(m2yc, rf, m2zc), rf * rf);
            rf += invFY;
            const u64* __restrict__ rowp =
                reinterpret_cast<const u64*>(&shz[(ib_s + i) * TP + jb_s]);
            #pragma unroll
            for (int j = 0; j < 7; j++) {
                const u64 zz = rowp[j];                 // (zn, zn^2)
                const u64 mg = add2(ar, bg[j]);         // (a+b, r2+g)
                const u64 pr = fma2(zz, mg, pc2p);      // (pc2+zn*m, zn^2*g)
                float lo, hi;
                unpack2(pr, lo, hi);                    // reg halves, no movs
                const float ss = lo + hi;
                const float dd = sqrt_abs(ss);
                if (j & 1) { s1a += dd; s2pa = add2(s2pa, pr); }
                else       { s1b += dd; s2pb = add2(s2pb, pr); }
            }
        }

        const float s1 = s1a + s1b;
        float l0, h0, l1, h1;
        unpack2(add2(s2pa, s2pb), l0, h0);
        const float s2 = l0 + h0;
        (void)l1; (void)h1;

        // var = (sum d^2 - (sum d)^2/49) / 48  (Bessel-corrected)
        const float mean = s1 * (1.0f / 49.0f);
        float var = fmaf(-mean, s1, s2) * (1.0f / 48.0f);
        var = fmaxf(var, 0.0f);
        total += (zc > 0.0f) ? sqrt_abs(var) : 0.0f;
    }

    // Deterministic warp shuffle reduction, then cross-warp via smem.
    #pragma unroll
    for (int k = 16; k > 0; k >>= 1)
        total += __shfl_down_sync(0xFFFFFFFFu, total, k);
    if ((tid & 31) == 0) red[tid >> 5] = total;
    __syncthreads();

    // Fused final reduction: last arriving block sums all partials in
    // fixed index order (deterministic), writes out, re-arms counter.
    if (tid == 0) {
        g_partials[blockIdx.y * GRIDX + blockIdx.x] =
            (red[0] + red[1]) + (red[2] + red[3]);
        __threadfence();
        const unsigned int t = atomicAdd(&g_count, 1u);
        s_last = (t == NPART - 1) ? 1u : 0u;
    }
    __syncthreads();

    if (s_last) {
        const volatile float* vp = g_partials;
        float s = 0.0f;
        for (int i = tid; i < NPART; i += NT) s += vp[i];
        #pragma unroll
        for (int k = 16; k > 0; k >>= 1)
            s += __shfl_down_sync(0xFFFFFFFFu, s, k);
        if ((tid & 31) == 0) red[tid >> 5] = s;
        __syncthreads();
        if (tid == 0) {
            out[0] = ((red[0] + red[1]) + (red[2] + red[3])) * 100.0f;
            g_count = 0;   // re-arm for next graph replay
        }
    }
}

extern "C" void kernel_launch(void* const* d_in, const int* in_sizes, int n_in,
                              void* d_out, int out_size) {
    const float* depth = (const float*)d_in[0];
    float* out = (float*)d_out;

    dim3 grid(GRIDX, GRIDY);
    dim3 block(BX, BY);
    stdev_kernel<<<grid, block>>>(depth, out);
}

// round 12
// speedup vs baseline: 1.0149x; 1.0149x over previous
#include <cuda_runtime.h>

// StDevLoss: 7x7 clamped-window 3D-point-distance std, summed, x100.
// depthin (1,1,480,640) fp32 -> scalar fp32. Single fused kernel.
// Round 11: fully packed f32x2 inner loop (FFMA2 quadratic eval, packed
// s2 accumulators), (z,z^2) float2 smem, 2 px/thread, 1200 blocks.

#define ROWS 480
#define COLS 640

#define BX 32
#define BY 4
#define NT (BX * BY)          // 128 threads
#define PIX_Y 8               // 2 pixels per thread
#define TW (BX + 6)           // 38
#define TH (PIX_Y + 6)        // 14
#define TP 40                 // shared row stride (float2 units)

#define GRIDX (COLS / BX)     // 20
#define GRIDY (ROWS / PIX_Y)  // 60
#define NPART (GRIDX * GRIDY) // 1200

__device__ float g_partials[NPART];
__device__ unsigned int g_count = 0;

typedef unsigned long long u64;

// sqrt(|x|): abs folds into the MUFU operand modifier; sqrt.approx(0)==0.
__device__ __forceinline__ float sqrt_abs(float x) {
    float r;
    asm("{\n\t.reg .f32 t;\n\tabs.f32 t, %1;\n\tsqrt.approx.f32 %0, t;\n\t}"
        : "=f"(r) : "f"(x));
    return r;
}
__device__ __forceinline__ u64 pack2(float lo, float hi) {
    u64 r;
    asm("mov.b64 %0, {%1, %2};" : "=l"(r) : "f"(lo), "f"(hi));
    return r;
}
__device__ __forceinline__ void unpack2(u64 v, float& lo, float& hi) {
    asm("mov.b64 {%0, %1}, %2;" : "=f"(lo), "=f"(hi) : "l"(v));
}
__device__ __forceinline__ u64 add2(u64 a, u64 b) {
    u64 r;
    asm("add.rn.f32x2 %0, %1, %2;" : "=l"(r) : "l"(a), "l"(b));
    return r;
}
__device__ __forceinline__ u64 fma2(u64 a, u64 b, u64 c) {
    u64 r;
    asm("fma.rn.f32x2 %0, %1, %2, %3;" : "=l"(r) : "l"(a), "l"(b), "l"(c));
    return r;
}

__global__ __launch_bounds__(NT, 8)
void stdev_kernel(const float* __restrict__ depth, float* __restrict__ out) {
    const float CXc   = 313.0447587080473f;
    const float CYc   = 238.44389626620386f;
    const float invFX = 1.0f / 582.6244816773795f;
    const float invFY = 1.0f / 582.6910327098864f;

    __shared__ float2 shz[TH * TP];      // (z, z^2)
    __shared__ float red[NT / 32];
    __shared__ unsigned int s_last;

    const int tx  = threadIdx.x;
    const int ty  = threadIdx.y;
    const int tid = ty * BX + tx;
    const int c0  = blockIdx.x * BX;
    const int r0  = blockIdx.y * PIX_Y;

    // Cooperative haloed (z, z^2) tile load. Clamped halo cells are never
    // read by the clamped-window indexing but must hold finite values.
    for (int i = tid; i < TH * TW; i += NT) {
        const int sr = i / TW;
        const int sc = i - sr * TW;
        const int gr = min(max(r0 - 3 + sr, 0), ROWS - 1);
        const int gc = min(max(c0 - 3 + sc, 0), COLS - 1);
        const float d = depth[gr * COLS + gc];
        const float z = (d > 0.0f && d < 1.01f) ? d * 1e-3f : 0.0f;
        shz[sr * TP + sc] = make_float2(z, z * z);
    }
    __syncthreads();

    const int c    = c0 + tx;
    const int jb   = min(max(c - 3, 0), COLS - 7);
    const int jb_s = jb - c0 + 3;
    const float cfc = ((float)c - CXc) * invFX;     // center column factor
    const float cf0 = ((float)jb - CXc) * invFX;    // window column base

    float total = 0.0f;

    #pragma unroll
    for (int p = 0; p < 2; p++) {
        const int r    = r0 + ty + p * BY;
        const int ib   = min(max(r - 3, 0), ROWS - 7);
        const int ib_s = ib - r0 + 3;

        const float zc = shz[(ty + p * BY + 3) * TP + (tx + 3)].x;
        const float xc = zc * cfc;
        const float yc = zc * (((float)r - CYc) * invFY);
        float pc2 = xc * xc;
        pc2 = fmaf(yc, yc, pc2);
        pc2 = fmaf(zc, zc, pc2);
        const u64 pc2p = pack2(pc2, 0.0f);
        const float m2xc = -2.0f * xc;
        const float m2yc = -2.0f * yc;
        const float m2zc = -2.0f * zc;

        // Per-column packed (b_j, g_j): b = -2*xc*cf, g = cf^2 + 1.
        u64 bg[7];
        {
            float cf = cf0;
            #pragma unroll
            for (int j = 0; j < 7; j++) {
                bg[j] = pack2(m2xc * cf, fmaf(cf, cf, 1.0f));
                cf += invFX;
            }
        }

        float s1a = 0.0f, s1b = 0.0f;          // sum d (dual chains)
        u64 s2pa = pack2(0.0f, 0.0f);          // packed sum of (lo, hi) parts
        u64 s2pb = pack2(0.0f, 0.0f);

        float rf = ((float)ib - CYc) * invFY;
        #pragma unroll
        for (int i = 0; i < 7; i++) {
            // Per-row packed (a_i, rf^2): a = -2*(yc*rf + zc).
            const u64 ar = pack2(fmaf(m2yc, rf, m2zc), rf * rf);
            rf += invFY;
            const u64* __restrict__ rowp =
                reinterpret_cast<const u64*>(&shz[(ib_s + i) * TP + jb_s]);
            #pragma unroll
            for (int j = 0; j < 7; j++) {
                const u64 zz = rowp[j];                 // (zn, zn^2)
                const u64 mg = add2(ar, bg[j]);         // (a+b, r2+g)
                const u64 pr = fma2(zz, mg, pc2p);      // (pc2+zn*m, zn^2*g)
                float lo, hi;
                unpack2(pr, lo, hi);                    // reg halves, no movs
                const float ss = lo + hi;
                const float dd = sqrt_abs(ss);
                if (j & 1) { s1a += dd; s2pa = add2(s2pa, pr); }
                else       { s1b += dd; s2pb = add2(s2pb, pr); }
            }
        }

        const float s1 = s1a + s1b;
        float l0, h0, l1, h1;
        unpack2(add2(s2pa, s2pb), l0, h0);
        const float s2 = l0 + h0;
        (void)l1; (void)h1;

        // var = (sum d^2 - (sum d)^2/49) / 48  (Bessel-corrected)
        const float mean = s1 * (1.0f / 49.0f);
        float var = fmaf(-mean, s1, s2) * (1.0f / 48.0f);
        var = fmaxf(var, 0.0f);
        total += (zc > 0.0f) ? sqrt_abs(var) : 0.0f;
    }

    // Deterministic warp shuffle reduction, then cross-warp via smem.
    #pragma unroll
    for (int k = 16; k > 0; k >>= 1)
        total += __shfl_down_sync(0xFFFFFFFFu, total, k);
    if ((tid & 31) == 0) red[tid >> 5] = total;
    __syncthreads();

    // Fused final reduction: last arriving block sums all partials in
    // fixed index order (deterministic), writes out, re-arms counter.
    if (tid == 0) {
        g_partials[blockIdx.y * GRIDX + blockIdx.x] =
            (red[0] + red[1]) + (red[2] + red[3]);
        __threadfence();
        const unsigned int t = atomicAdd(&g_count, 1u);
        s_last = (t == NPART - 1) ? 1u : 0u;
    }
    __syncthreads();

    if (s_last) {
        const volatile float* vp = g_partials;
        float s = 0.0f;
        for (int i = tid; i < NPART; i += NT) s += vp[i];
        #pragma unroll
        for (int k = 16; k > 0; k >>= 1)
            s += __shfl_down_sync(0xFFFFFFFFu, s, k);
        if ((tid & 31) == 0) red[tid >> 5] = s;
        __syncthreads();
        if (tid == 0) {
            out[0] = ((red[0] + red[1]) + (red[2] + red[3])) * 100.0f;
            g_count = 0;   // re-arm for next graph replay
        }
    }
}

extern "C" void kernel_launch(void* const* d_in, const int* in_sizes, int n_in,
                              void* d_out, int out_size) {
    const float* depth = (const float*)d_in[0];
    float* out = (float*)d_out;

    dim3 grid(GRIDX, GRIDY);
    dim3 block(BX, BY);
    stdev_kernel<<<grid, block>>>(depth, out);
}

// round 13
// speedup vs baseline: 1.1310x; 1.1143x over previous
#include <cuda_runtime.h>

// StDevLoss: 7x7 clamped-window 3D-point-distance std, summed, x100.
// depthin (1,1,480,640) fp32 -> scalar fp32. Single fused kernel.
// Round 13: consecutive-row pixel pairing. The two windows share 6 of 7
// rows, so each (row, col) smem load + the center-independent quadratic
// coefficient are computed ONCE and serve both pixels.

#define ROWS 480
#define COLS 640

#define BX 32
#define BY 4
#define NT (BX * BY)          // 128 threads; thread owns rows r0+2ty, +1
#define PIX_Y 8
#define TW (BX + 6)           // 38
#define TH (PIX_Y + 6)        // 14
#define TP 40                 // shared row stride (float2 units)

#define GRIDX (COLS / BX)     // 20
#define GRIDY (ROWS / PIX_Y)  // 60
#define NPART (GRIDX * GRIDY) // 1200

__device__ float g_partials[NPART];
__device__ unsigned int g_count = 0;

// sqrt(|x|): abs folds into the MUFU operand modifier; sqrt.approx(0)==0.
__device__ __forceinline__ float sqrt_abs(float x) {
    float r;
    asm("{\n\t.reg .f32 t;\n\tabs.f32 t, %1;\n\tsqrt.approx.f32 %0, t;\n\t}"
        : "=f"(r) : "f"(x));
    return r;
}

struct Pix {
    float pc2, m2x, m2y, m2z;   // center terms
    float s1a, s1b, s2a, s2b;   // dual accumulator chains
};

__device__ __forceinline__ void init_pix(Pix& p, float zc, float cfc, float rfc) {
    const float xc = zc * cfc;
    const float yc = zc * rfc;
    float pc2 = xc * xc;
    pc2 = fmaf(yc, yc, pc2);
    pc2 = fmaf(zc, zc, pc2);
    p.pc2 = pc2;
    p.m2x = -2.0f * xc;
    p.m2y = -2.0f * yc;
    p.m2z = -2.0f * zc;
    p.s1a = p.s1b = p.s2a = p.s2b = 0.0f;
}

// Process one window row for up to two pixels. P0/P1 compile-time.
template <bool P0, bool P1>
__device__ __forceinline__ void do_row(const float2* __restrict__ rowp,
                                       const float* __restrict__ cf,
                                       float rf, Pix& p0, Pix& p1) {
    const float r2p1 = fmaf(rf, rf, 1.0f);
    const float a0 = P0 ? fmaf(p0.m2y, rf, p0.m2z) : 0.0f;
    const float a1 = P1 ? fmaf(p1.m2y, rf, p1.m2z) : 0.0f;
    #pragma unroll
    for (int j = 0; j < 7; j++) {
        const float2 zz = rowp[j];                    // (zn, zn^2): one LDS.64
        const float qg = fmaf(cf[j], cf[j], r2p1);    // cf^2 + rf^2 + 1 (shared)
        const float q  = zz.y * qg;                   // zn^2 * qg     (shared)
        if (P0) {
            const float m  = fmaf(p0.m2x, cf[j], a0);
            const float ss = fmaf(zz.x, m, q) + p0.pc2;
            const float dd = sqrt_abs(ss);
            if (j & 1) { p0.s1a += dd; p0.s2a += ss; }
            else       { p0.s1b += dd; p0.s2b += ss; }
        }
        if (P1) {
            const float m  = fmaf(p1.m2x, cf[j], a1);
            const float ss = fmaf(zz.x, m, q) + p1.pc2;
            const float dd = sqrt_abs(ss);
            if (j & 1) { p1.s1a += dd; p1.s2a += ss; }
            else       { p1.s1b += dd; p1.s2b += ss; }
        }
    }
}

__device__ __forceinline__ float finish_pix(const Pix& p, float zc) {
    const float s1 = (p.s1a + p.s1b);
    const float s2 = (p.s2a + p.s2b);
    const float mean = s1 * (1.0f / 49.0f);
    float var = fmaf(-mean, s1, s2) * (1.0f / 48.0f);
    var = fmaxf(var, 0.0f);
    return (zc > 0.0f) ? sqrt_abs(var) : 0.0f;
}

__global__ __launch_bounds__(NT, 9)
void stdev_kernel(const float* __restrict__ depth, float* __restrict__ out) {
    const float CXc   = 313.0447587080473f;
    const float CYc   = 238.44389626620386f;
    const float invFX = 1.0f / 582.6244816773795f;
    const float invFY = 1.0f / 582.6910327098864f;

    __shared__ float2 shz[TH * TP];      // (z, z^2)
    __shared__ float red[NT / 32];
    __shared__ unsigned int s_last;

    const int tx  = threadIdx.x;
    const int ty  = threadIdx.y;
    const int tid = ty * BX + tx;
    const int c0  = blockIdx.x * BX;
    const int r0  = blockIdx.y * PIX_Y;

    // Cooperative haloed (z, z^2) tile load. Clamped halo cells are never
    // read by the clamped-window indexing but must hold finite values.
    for (int i = tid; i < TH * TW; i += NT) {
        const int sr = i / TW;
        const int sc = i - sr * TW;
        const int gr = min(max(r0 - 3 + sr, 0), ROWS - 1);
        const int gc = min(max(c0 - 3 + sc, 0), COLS - 1);
        const float d = depth[gr * COLS + gc];
        const float z = (d > 0.0f && d < 1.01f) ? d * 1e-3f : 0.0f;
        shz[sr * TP + sc] = make_float2(z, z * z);
    }
    __syncthreads();

    const int c    = c0 + tx;
    const int jb   = min(max(c - 3, 0), COLS - 7);
    const int jb_s = jb - c0 + 3;
    const float cfc = ((float)c - CXc) * invFX;

    float cf[7];
    {
        float v = ((float)jb - CXc) * invFX;
        #pragma unroll
        for (int j = 0; j < 7; j++) { cf[j] = v; v += invFX; }
    }

    // Two consecutive pixel rows per thread (warp-uniform: warp == one ty).
    const int ra  = r0 + 2 * ty;
    const int rb  = ra + 1;
    const int ib0 = min(max(ra - 3, 0), ROWS - 7);
    const int ib1 = min(max(rb - 3, 0), ROWS - 7);
    const int d10 = ib1 - ib0;                 // 0 or 1, warp-uniform
    const int base_s = ib0 - r0 + 3;           // smem row of window row t=0

    const float zc0 = shz[(2 * ty + 3) * TP + (tx + 3)].x;
    const float zc1 = shz[(2 * ty + 4) * TP + (tx + 3)].x;

    Pix p0, p1;
    init_pix(p0, zc0, cfc, ((float)ra - CYc) * invFY);
    init_pix(p1, zc1, cfc, ((float)rb - CYc) * invFY);

    const float2* __restrict__ rp0 = &shz[base_s * TP + jb_s];
    const float rf0 = ((float)ib0 - CYc) * invFY;

    // Row t=0: p0 always; p1 only when windows coincide (d10 == 0).
    if (d10 == 0) do_row<true,  true >(rp0, cf, rf0, p0, p1);
    else          do_row<true,  false>(rp0, cf, rf0, p0, p1);

    // Rows t=1..6: both pixels always active.
    #pragma unroll
    for (int t = 1; t <= 6; t++)
        do_row<true, true>(rp0 + t * TP, cf, rf0 + (float)t * invFY, p0, p1);

    // Row t=7: p1 only, and only when windows are offset (d10 == 1).
    if (d10 == 1)
        do_row<false, true>(rp0 + 7 * TP, cf, rf0 + 7.0f * invFY, p0, p1);

    float total = finish_pix(p0, zc0) + finish_pix(p1, zc1);

    // Deterministic warp shuffle reduction, then cross-warp via smem.
    #pragma unroll
    for (int k = 16; k > 0; k >>= 1)
        total += __shfl_down_sync(0xFFFFFFFFu, total, k);
    if ((tid & 31) == 0) red[tid >> 5] = total;
    __syncthreads();

    // Fused final reduction: last arriving block sums all partials in
    // fixed index order (deterministic), writes out, re-arms counter.
    if (tid == 0) {
        g_partials[blockIdx.y * GRIDX + blockIdx.x] =
            (red[0] + red[1]) + (red[2] + red[3]);
        __threadfence();
        const unsigned int t = atomicAdd(&g_count, 1u);
        s_last = (t == NPART - 1) ? 1u : 0u;
    }
    __syncthreads();

    if (s_last) {
        const volatile float* vp = g_partials;
        float s = 0.0f;
        for (int i = tid; i < NPART; i += NT) s += vp[i];
        #pragma unroll
        for (int k = 16; k > 0; k >>= 1)
            s += __shfl_down_sync(0xFFFFFFFFu, s, k);
        if ((tid & 31) == 0) red[tid >> 5] = s;
        __syncthreads();
        if (tid == 0) {
            out[0] = ((red[0] + red[1]) + (red[2] + red[3])) * 100.0f;
            g_count = 0;   // re-arm for next graph replay
        }
    }
}

extern "C" void kernel_launch(void* const* d_in, const int* in_sizes, int n_in,
                              void* d_out, int out_size) {
    const float* depth = (const float*)d_in[0];
    float* out = (float*)d_out;

    dim3 grid(GRIDX, GRIDY);
    dim3 block(BX, BY);
    stdev_kernel<<<grid, block>>>(depth, out);
}

// round 14
// speedup vs baseline: 1.1501x; 1.0169x over previous
#include <cuda_runtime.h>

// StDevLoss: 7x7 clamped-window 3D-point-distance std, summed, x100.
// depthin (1,1,480,640) fp32 -> scalar fp32. Single fused kernel.
// Round 14: R13 row-paired base + div-free halo fill + pc2 folded into
// the per-pixel quadratic term (14 issues per neighbor-pair).

#define ROWS 480
#define COLS 640

#define BX 32
#define BY 4
#define NT (BX * BY)          // 128 threads; thread owns rows r0+2ty, +1
#define PIX_Y 8
#define TW (BX + 6)           // 38
#define TH (PIX_Y + 6)        // 14
#define TP 40                 // shared row stride (float2 units)

#define GRIDX (COLS / BX)     // 20
#define GRIDY (ROWS / PIX_Y)  // 60
#define NPART (GRIDX * GRIDY) // 1200

__device__ float g_partials[NPART];
__device__ unsigned int g_count = 0;

// sqrt(|x|): abs folds into the MUFU operand modifier; sqrt.approx(0)==0.
__device__ __forceinline__ float sqrt_abs(float x) {
    float r;
    asm("{\n\t.reg .f32 t;\n\tabs.f32 t, %1;\n\tsqrt.approx.f32 %0, t;\n\t}"
        : "=f"(r) : "f"(x));
    return r;
}

struct Pix {
    float pc2, m2x, m2y, m2z;   // center terms
    float s1a, s1b, s2a, s2b;   // dual accumulator chains
};

__device__ __forceinline__ void init_pix(Pix& p, float zc, float cfc, float rfc) {
    const float xc = zc * cfc;
    const float yc = zc * rfc;
    float pc2 = xc * xc;
    pc2 = fmaf(yc, yc, pc2);
    pc2 = fmaf(zc, zc, pc2);
    p.pc2 = pc2;
    p.m2x = -2.0f * xc;
    p.m2y = -2.0f * yc;
    p.m2z = -2.0f * zc;
    p.s1a = p.s1b = p.s2a = p.s2b = 0.0f;
}

// One window row for up to two pixels (P0/P1 compile-time).
// Per j: LDS.64 + shared qg FFMA + per-pixel {q, m, ss} FFMAs + MUFU + 2 FADD.
template <bool P0, bool P1>
__device__ __forceinline__ void do_row(const float2* __restrict__ rowp,
                                       const float* __restrict__ cf,
                                       float rf, Pix& p0, Pix& p1) {
    const float r2p1 = fmaf(rf, rf, 1.0f);
    const float a0 = P0 ? fmaf(p0.m2y, rf, p0.m2z) : 0.0f;
    const float a1 = P1 ? fmaf(p1.m2y, rf, p1.m2z) : 0.0f;
    #pragma unroll
    for (int j = 0; j < 7; j++) {
        const float2 zz = rowp[j];                    // (zn, zn^2): one LDS.64
        const float qg = fmaf(cf[j], cf[j], r2p1);    // cf^2 + rf^2 + 1 (shared)
        if (P0) {
            const float q  = fmaf(zz.y, qg, p0.pc2);  // zn^2*qg + pc2
            const float m  = fmaf(p0.m2x, cf[j], a0);
            const float ss = fmaf(zz.x, m, q);
            const float dd = sqrt_abs(ss);
            if (j & 1) { p0.s1a += dd; p0.s2a += ss; }
            else       { p0.s1b += dd; p0.s2b += ss; }
        }
        if (P1) {
            const float q  = fmaf(zz.y, qg, p1.pc2);
            const float m  = fmaf(p1.m2x, cf[j], a1);
            const float ss = fmaf(zz.x, m, q);
            const float dd = sqrt_abs(ss);
            if (j & 1) { p1.s1a += dd; p1.s2a += ss; }
            else       { p1.s1b += dd; p1.s2b += ss; }
        }
    }
}

__device__ __forceinline__ float finish_pix(const Pix& p, float zc) {
    const float s1 = (p.s1a + p.s1b);
    const float s2 = (p.s2a + p.s2b);
    const float mean = s1 * (1.0f / 49.0f);
    float var = fmaf(-mean, s1, s2) * (1.0f / 48.0f);
    var = fmaxf(var, 0.0f);
    return (zc > 0.0f) ? sqrt_abs(var) : 0.0f;
}

__global__ __launch_bounds__(NT, 9)
void stdev_kernel(const float* __restrict__ depth, float* __restrict__ out) {
    const float CXc   = 313.0447587080473f;
    const float CYc   = 238.44389626620386f;
    const float invFX = 1.0f / 582.6244816773795f;
    const float invFY = 1.0f / 582.6910327098864f;

    __shared__ float2 shz[TH * TP];      // (z, z^2)
    __shared__ float red[NT / 32];
    __shared__ unsigned int s_last;

    const int tx  = threadIdx.x;
    const int ty  = threadIdx.y;
    const int tid = ty * BX + tx;
    const int c0  = blockIdx.x * BX;
    const int r0  = blockIdx.y * PIX_Y;

    // Div-free cooperative haloed (z, z^2) tile load. Clamped halo cells
    // are never read by the clamped-window logic but must be finite.
    #pragma unroll
    for (int sr = 0; sr < TH; sr += BY) {
        const int srr = sr + ty;
        if (srr < TH) {
            const int gr = min(max(r0 - 3 + srr, 0), ROWS - 1);
            const float* __restrict__ drow = depth + gr * COLS;
            #pragma unroll
            for (int sc0 = 0; sc0 < TW; sc0 += BX) {
                const int sc = sc0 + tx;
                if (sc < TW) {
                    const int gc = min(max(c0 - 3 + sc, 0), COLS - 1);
                    const float d = drow[gc];
                    const float z = (d > 0.0f && d < 1.01f) ? d * 1e-3f : 0.0f;
                    shz[srr * TP + sc] = make_float2(z, z * z);
                }
            }
        }
    }
    __syncthreads();

    const int c    = c0 + tx;
    const int jb   = min(max(c - 3, 0), COLS - 7);
    const int jb_s = jb - c0 + 3;
    const float cfc = ((float)c - CXc) * invFX;

    float cf[7];
    {
        float v = ((float)jb - CXc) * invFX;
        #pragma unroll
        for (int j = 0; j < 7; j++) { cf[j] = v; v += invFX; }
    }

    // Two consecutive pixel rows per thread (warp-uniform: warp == one ty).
    const int ra  = r0 + 2 * ty;
    const int rb  = ra + 1;
    const int ib0 = min(max(ra - 3, 0), ROWS - 7);
    const int ib1 = min(max(rb - 3, 0), ROWS - 7);
    const int d10 = ib1 - ib0;                 // 0 or 1, warp-uniform
    const int base_s = ib0 - r0 + 3;           // smem row of window row t=0

    const float zc0 = shz[(2 * ty + 3) * TP + (tx + 3)].x;
    const float zc1 = shz[(2 * ty + 4) * TP + (tx + 3)].x;

    Pix p0, p1;
    init_pix(p0, zc0, cfc, ((float)ra - CYc) * invFY);
    init_pix(p1, zc1, cfc, ((float)rb - CYc) * invFY);

    const float2* __restrict__ rp0 = &shz[base_s * TP + jb_s];
    const float rf0 = ((float)ib0 - CYc) * invFY;

    // Row t=0: p0 always; p1 only when windows coincide (d10 == 0).
    if (d10 == 0) do_row<true,  true >(rp0, cf, rf0, p0, p1);
    else          do_row<true,  false>(rp0, cf, rf0, p0, p1);

    // Rows t=1..6: both pixels always active.
    #pragma unroll
    for (int t = 1; t <= 6; t++)
        do_row<true, true>(rp0 + t * TP, cf, rf0 + (float)t * invFY, p0, p1);

    // Row t=7: p1 only, and only when windows are offset (d10 == 1).
    if (d10 == 1)
        do_row<false, true>(rp0 + 7 * TP, cf, rf0 + 7.0f * invFY, p0, p1);

    float total = finish_pix(p0, zc0) + finish_pix(p1, zc1);

    // Deterministic warp shuffle reduction, then cross-warp via smem.
    #pragma unroll
    for (int k = 16; k > 0; k >>= 1)
        total += __shfl_down_sync(0xFFFFFFFFu, total, k);
    if ((tid & 31) == 0) red[tid >> 5] = total;
    __syncthreads();

    // Fused final reduction: last arriving block sums all partials in
    // fixed index order (deterministic), writes out, re-arms counter.
    if (tid == 0) {
        g_partials[blockIdx.y * GRIDX + blockIdx.x] =
            (red[0] + red[1]) + (red[2] + red[3]);
        __threadfence();
        const unsigned int t = atomicAdd(&g_count, 1u);
        s_last = (t == NPART - 1) ? 1u : 0u;
    }
    __syncthreads();

    if (s_last) {
        const volatile float* vp = g_partials;
        float s = 0.0f;
        for (int i = tid; i < NPART; i += NT) s += vp[i];
        #pragma unroll
        for (int k = 16; k > 0; k >>= 1)
            s += __shfl_down_sync(0xFFFFFFFFu, s, k);
        if ((tid & 31) == 0) red[tid >> 5] = s;
        __syncthreads();
        if (tid == 0) {
            out[0] = ((red[0] + red[1]) + (red[2] + red[3])) * 100.0f;
            g_count = 0;   // re-arm for next graph replay
        }
    }
}

extern "C" void kernel_launch(void* const* d_in, const int* in_sizes, int n_in,
                              void* d_out, int out_size) {
    const float* depth = (const float*)d_in[0];
    float* out = (float*)d_out;

    dim3 grid(GRIDX, GRIDY);
    dim3 block(BX, BY);
    stdev_kernel<<<grid, block>>>(depth, out);
}

// round 15
// speedup vs baseline: 1.1724x; 1.0194x over previous
#include <cuda_runtime.h>

// StDevLoss: 7x7 clamped-window 3D-point-distance std, summed, x100.
// depthin (1,1,480,640) fp32 -> scalar fp32. Single fused kernel.
// Round 15: row-paired pixels evaluated as f32x2 SIMD lanes. smem holds
// (z,z) so LDS.64 broadcasts; all lane packs hoisted to thread/row setup.

#define ROWS 480
#define COLS 640

#define BX 32
#define BY 4
#define NT (BX * BY)          // 128 threads; thread owns rows r0+2ty, +1
#define PIX_Y 8
#define TW (BX + 6)           // 38
#define TH (PIX_Y + 6)        // 14
#define TP 40                 // shared row stride (float2 units)

#define GRIDX (COLS / BX)     // 20
#define GRIDY (ROWS / PIX_Y)  // 60
#define NPART (GRIDX * GRIDY) // 1200

__device__ float g_partials[NPART];
__device__ unsigned int g_count = 0;

typedef unsigned long long u64;

// sqrt(|x|): abs folds into the MUFU operand modifier; sqrt.approx(0)==0.
__device__ __forceinline__ float sqrt_abs(float x) {
    float r;
    asm("{\n\t.reg .f32 t;\n\tabs.f32 t, %1;\n\tsqrt.approx.f32 %0, t;\n\t}"
        : "=f"(r) : "f"(x));
    return r;
}
__device__ __forceinline__ u64 pack2(float lo, float hi) {
    u64 r;
    asm("mov.b64 %0, {%1, %2};" : "=l"(r) : "f"(lo), "f"(hi));
    return r;
}
__device__ __forceinline__ void unpack2(u64 v, float& lo, float& hi) {
    asm("mov.b64 {%0, %1}, %2;" : "=f"(lo), "=f"(hi) : "l"(v));
}
__device__ __forceinline__ u64 add2(u64 a, u64 b) {
    u64 r;
    asm("add.rn.f32x2 %0, %1, %2;" : "=l"(r) : "l"(a), "l"(b));
    return r;
}
__device__ __forceinline__ u64 fma2(u64 a, u64 b, u64 c) {
    u64 r;
    asm("fma.rn.f32x2 %0, %1, %2, %3;" : "=l"(r) : "l"(a), "l"(b), "l"(c));
    return r;
}

// Packed row: both pixels active. Per j: LDS.64 + 4 fma2 + 2 MUFU + 2 FADD
// + 1 add2 = 10 issues for 2 neighbors.
__device__ __forceinline__ void row2(const u64* __restrict__ rowp,
                                     const u64* __restrict__ cfd, float rf,
                                     float m2y0, float m2z0,
                                     float m2y1, float m2z1,
                                     u64 m2x01, u64 pc201,
                                     float& s1_0, float& s1_1, u64& s2p) {
    const float r2p1 = fmaf(rf, rf, 1.0f);
    const u64 r2p101 = pack2(r2p1, r2p1);
    const u64 a01 = pack2(fmaf(m2y0, rf, m2z0), fmaf(m2y1, rf, m2z1));
    #pragma unroll
    for (int j = 0; j < 7; j++) {
        const u64 zz = rowp[j];                      // (zn, zn) broadcast
        const u64 qg = fma2(cfd[j], cfd[j], r2p101); // cf^2 + rf^2 + 1
        const u64 m  = fma2(m2x01, cfd[j], a01);     // m2x*cf + a
        const u64 t  = fma2(zz, qg, m);              // zn*qg + m
        const u64 ss = fma2(zz, t, pc201);           // zn*t + pc2
        float ss0, ss1;
        unpack2(ss, ss0, ss1);                       // register halves
        s1_0 += sqrt_abs(ss0);
        s1_1 += sqrt_abs(ss1);
        s2p = add2(s2p, ss);
    }
}

// Scalar row: one pixel active (clamped-edge rows; runs at most once/thread).
__device__ __forceinline__ void row1(const u64* __restrict__ rowp,
                                     const u64* __restrict__ cfd, float rf,
                                     float m2y, float m2z, float m2x,
                                     float pc2, float& s1, float& s2e) {
    const float r2p1 = fmaf(rf, rf, 1.0f);
    const float a = fmaf(m2y, rf, m2z);
    #pragma unroll
    for (int j = 0; j < 7; j++) {
        float cf, cfh, zn, znh;
        unpack2(cfd[j], cf, cfh);
        unpack2(rowp[j], zn, znh);
        (void)cfh; (void)znh;
        const float qg = fmaf(cf, cf, r2p1);
        const float m  = fmaf(m2x, cf, a);
        const float t  = fmaf(zn, qg, m);
        const float ss = fmaf(zn, t, pc2);
        s1 += sqrt_abs(ss);
        s2e += ss;
    }
}

__global__ __launch_bounds__(NT, 9)
void stdev_kernel(const float* __restrict__ depth, float* __restrict__ out) {
    const float CXc   = 313.0447587080473f;
    const float CYc   = 238.44389626620386f;
    const float invFX = 1.0f / 582.6244816773795f;
    const float invFY = 1.0f / 582.6910327098864f;

    __shared__ float2 shz[TH * TP];      // (z, z) duplicated
    __shared__ float red[NT / 32];
    __shared__ unsigned int s_last;

    const int tx  = threadIdx.x;
    const int ty  = threadIdx.y;
    const int tid = ty * BX + tx;
    const int c0  = blockIdx.x * BX;
    const int r0  = blockIdx.y * PIX_Y;

    // Div-free cooperative haloed (z, z) tile load. Clamped halo cells are
    // never read by the clamped-window logic but must be finite.
    #pragma unroll
    for (int sr = 0; sr < TH; sr += BY) {
        const int srr = sr + ty;
        if (srr < TH) {
            const int gr = min(max(r0 - 3 + srr, 0), ROWS - 1);
            const float* __restrict__ drow = depth + gr * COLS;
            #pragma unroll
            for (int sc0 = 0; sc0 < TW; sc0 += BX) {
                const int sc = sc0 + tx;
                if (sc < TW) {
                    const int gc = min(max(c0 - 3 + sc, 0), COLS - 1);
                    const float d = drow[gc];
                    const float z = (d > 0.0f && d < 1.01f) ? d * 1e-3f : 0.0f;
                    shz[srr * TP + sc] = make_float2(z, z);
                }
            }
        }
    }
    __syncthreads();

    const int c    = c0 + tx;
    const int jb   = min(max(c - 3, 0), COLS - 7);
    const int jb_s = jb - c0 + 3;
    const float cfc = ((float)c - CXc) * invFX;

    // Packed per-column factors (cf_j, cf_j).
    u64 cfd[7];
    {
        float v = ((float)jb - CXc) * invFX;
        #pragma unroll
        for (int j = 0; j < 7; j++) { cfd[j] = pack2(v, v); v += invFX; }
    }

    // Two consecutive pixel rows per thread (warp-uniform: warp == one ty).
    const int ra  = r0 + 2 * ty;
    const int rb  = ra + 1;
    const int ib0 = min(max(ra - 3, 0), ROWS - 7);
    const int ib1 = min(max(rb - 3, 0), ROWS - 7);
    const int d10 = ib1 - ib0;                 // 0 or 1, warp-uniform
    const int base_s = ib0 - r0 + 3;

    const float zc0 = shz[(2 * ty + 3) * TP + (tx + 3)].x;
    const float zc1 = shz[(2 * ty + 4) * TP + (tx + 3)].x;

    // Per-pixel center terms.
    const float xc0 = zc0 * cfc, yc0 = zc0 * (((float)ra - CYc) * invFY);
    const float xc1 = zc1 * cfc, yc1 = zc1 * (((float)rb - CYc) * invFY);
    float pc20 = xc0 * xc0; pc20 = fmaf(yc0, yc0, pc20); pc20 = fmaf(zc0, zc0, pc20);
    float pc21 = xc1 * xc1; pc21 = fmaf(yc1, yc1, pc21); pc21 = fmaf(zc1, zc1, pc21);
    const float m2x0 = -2.0f * xc0, m2y0 = -2.0f * yc0, m2z0 = -2.0f * zc0;
    const float m2x1 = -2.0f * xc1, m2y1 = -2.0f * yc1, m2z1 = -2.0f * zc1;
    const u64 m2x01 = pack2(m2x0, m2x1);
    const u64 pc201 = pack2(pc20, pc21);

    float s1_0 = 0.0f, s1_1 = 0.0f;
    u64 s2p = pack2(0.0f, 0.0f);
    float s2e0 = 0.0f, s2e1 = 0.0f;    // edge-row side sums

    const u64* __restrict__ rp0 =
        reinterpret_cast<const u64*>(&shz[base_s * TP + jb_s]);
    const float rf0 = ((float)ib0 - CYc) * invFY;

    if (d10 == 0) {
        // Windows coincide: all 7 rows packed.
        #pragma unroll
        for (int t = 0; t < 7; t++)
            row2(rp0 + t * TP, cfd, rf0 + (float)t * invFY,
                 m2y0, m2z0, m2y1, m2z1, m2x01, pc201, s1_0, s1_1, s2p);
    } else {
        // Offset windows: row 0 p0-only, rows 1..6 packed, row 7 p1-only.
        row1(rp0, cfd, rf0, m2y0, m2z0, m2x0, pc20, s1_0, s2e0);
        #pragma unroll
        for (int t = 1; t <= 6; t++)
            row2(rp0 + t * TP, cfd, rf0 + (float)t * invFY,
                 m2y0, m2z0, m2y1, m2z1, m2x01, pc201, s1_0, s1_1, s2p);
        row1(rp0 + 7 * TP, cfd, rf0 + 7.0f * invFY,
             m2y1, m2z1, m2x1, pc21, s1_1, s2e1);
    }

    float s2_0, s2_1;
    unpack2(s2p, s2_0, s2_1);
    s2_0 += s2e0;
    s2_1 += s2e1;

    // var = (sum d^2 - (sum d)^2/49) / 48  (Bessel-corrected), per pixel.
    float total;
    {
        const float mean0 = s1_0 * (1.0f / 49.0f);
        float var0 = fmaf(-mean0, s1_0, s2_0) * (1.0f / 48.0f);
        var0 = fmaxf(var0, 0.0f);
        const float mean1 = s1_1 * (1.0f / 49.0f);
        float var1 = fmaf(-mean1, s1_1, s2_1) * (1.0f / 48.0f);
        var1 = fmaxf(var1, 0.0f);
        total  = (zc0 > 0.0f) ? sqrt_abs(var0) : 0.0f;
        total += (zc1 > 0.0f) ? sqrt_abs(var1) : 0.0f;
    }

    // Deterministic warp shuffle reduction, then cross-warp via smem.
    #pragma unroll
    for (int k = 16; k > 0; k >>= 1)
        total += __shfl_down_sync(0xFFFFFFFFu, total, k);
    if ((tid & 31) == 0) red[tid >> 5] = total;
    __syncthreads();

    // Fused final reduction: last arriving block sums all partials in
    // fixed index order (deterministic), writes out, re-arms counter.
    if (tid == 0) {
        g_partials[blockIdx.y * GRIDX + blockIdx.x] =
            (red[0] + red[1]) + (red[2] + red[3]);
        __threadfence();
        const unsigned int t = atomicAdd(&g_count, 1u);
        s_last = (t == NPART - 1) ? 1u : 0u;
    }
    __syncthreads();

    if (s_last) {
        const volatile float* vp = g_partials;
        float s = 0.0f;
        for (int i = tid; i < NPART; i += NT) s += vp[i];
        #pragma unroll
        for (int k = 16; k > 0; k >>= 1)
            s += __shfl_down_sync(0xFFFFFFFFu, s, k);
        if ((tid & 31) == 0) red[tid >> 5] = s;
        __syncthreads();
        if (tid == 0) {
            out[0] = ((red[0] + red[1]) + (red[2] + red[3])) * 100.0f;
            g_count = 0;   // re-arm for next graph replay
        }
    }
}

extern "C" void kernel_launch(void* const* d_in, const int* in_sizes, int n_in,
                              void* d_out, int out_size) {
    const float* depth = (const float*)d_in[0];
    float* out = (float*)d_out;

    dim3 grid(GRIDX, GRIDY);
    dim3 block(BX, BY);
    stdev_kernel<<<grid, block>>>(depth, out);
}